// round 3
// baseline (speedup 1.0000x reference)
#include <cuda_runtime.h>
#include <math.h>

// ---------------------------------------------------------------------------
// QConv2D: 4-qubit quantum circuit applied to every 2x2 patch of x(32,1,128,128)
//
// Math: state after AngleEmbedding is product state with real part
//   r_i = prod_w t_w[b_w],  t=(cos x/2, sin x/2), phase (-i)^popc(i).
// Constant circuit => Z_w = sum_{ij} A_w[i,j] r_i r_j (real quadratic form).
// Half-angle -> full-angle basis (1, cos x, sin x):
//   Z_w = P_L^T B_w P_R, P = g_top (x) g_bot (9-vec), g=(1,cos,sin).
// B_w (4 x 9 x 9) depends only on params -> computed once on device.
// ---------------------------------------------------------------------------

__device__ float d_B[4 * 81];  // [w][a][b], a=3*k0+k2 (left col), b=3*k1+k3

// ---------------------------- precompute kernel ----------------------------
__global__ void qconv_precompute(const float* __restrict__ params) {
    __shared__ float2 shU[16][16];     // shU[k][col] : U[k, col]
    __shared__ float  shA[4][16][16];  // A_w[i][j]
    int tid = threadIdx.x;

    // Phase 1: 16 threads, each simulates one basis column through the
    // constant part of the circuit (2 layers of RX/RZ per wire + CNOT chain).
    if (tid < 16) {
        float2 u[16];
#pragma unroll
        for (int k = 0; k < 16; k++) u[k] = make_float2(k == tid ? 1.f : 0.f, 0.f);
#pragma unroll
        for (int l = 0; l < 2; l++) {
#pragma unroll
            for (int w = 0; w < 4; w++) {
                float th_rx = params[(l * 4 + w) * 2 + 0];
                float th_rz = params[(l * 4 + w) * 2 + 1];
                float s, c;
                sincosf(0.5f * th_rx, &s, &c);
                const int m = 1 << (3 - w);
                // RX(theta) on wire w:  new0 = c*a0 - i s*a1 ; new1 = c*a1 - i s*a0
#pragma unroll
                for (int k = 0; k < 16; k++) {
                    if (!(k & m)) {
                        float2 a0 = u[k], a1 = u[k | m];
                        u[k]     = make_float2(c * a0.x + s * a1.y, c * a0.y - s * a1.x);
                        u[k | m] = make_float2(c * a1.x + s * a0.y, c * a1.y - s * a0.x);
                    }
                }
                float sz, cz;
                sincosf(0.5f * th_rz, &sz, &cz);
                // RZ: phase exp(-i t/2) on bit0, exp(+i t/2) on bit1
#pragma unroll
                for (int k = 0; k < 16; k++) {
                    float ps = (k & m) ? sz : -sz;
                    float2 a = u[k];
                    u[k] = make_float2(a.x * cz - a.y * ps, a.x * ps + a.y * cz);
                }
            }
            // CNOT(control = w+1, target = w) for w = 0,1,2 (in order)
#pragma unroll
            for (int w = 0; w < 3; w++) {
                const int cm = 1 << (2 - w);  // control wire w+1
                const int tm = 1 << (3 - w);  // target wire w
#pragma unroll
                for (int k = 0; k < 16; k++) {
                    if ((k & cm) && !(k & tm)) {
                        float2 tmp = u[k]; u[k] = u[k | tm]; u[k | tm] = tmp;
                    }
                }
            }
        }
#pragma unroll
        for (int k = 0; k < 16; k++) shU[k][tid] = u[k];
    }
    __syncthreads();

    // Phase 2: 256 threads, A_w[i][j] = Re( i^{popc(i)-popc(j)} * M_w[i,j] ),
    //   M_w[i,j] = sum_k d_w(k) conj(U[k,i]) U[k,j],  d_w(k) = +-1 (Z on wire w)
    if (tid < 256) {
        int i = tid >> 4, j = tid & 15;
        float ar[4] = {0, 0, 0, 0}, ai[4] = {0, 0, 0, 0};
#pragma unroll
        for (int k = 0; k < 16; k++) {
            float2 ui = shU[k][i], uj = shU[k][j];
            float cr = ui.x * uj.x + ui.y * uj.y;  // Re(conj(ui)*uj)
            float ci = ui.x * uj.y - ui.y * uj.x;  // Im
#pragma unroll
            for (int w = 0; w < 4; w++) {
                float sgn = (k & (1 << (3 - w))) ? -1.f : 1.f;
                ar[w] += sgn * cr;
                ai[w] += sgn * ci;
            }
        }
        int ph = (__popc(i) - __popc(j)) & 3;
#pragma unroll
        for (int w = 0; w < 4; w++) {
            float re;
            if (ph == 0)      re =  ar[w];
            else if (ph == 1) re = -ai[w];   // Re(i*z) = -Im z
            else if (ph == 2) re = -ar[w];
            else              re =  ai[w];
            shA[w][i][j] = re;
        }
    }
    __syncthreads();

    // Phase 3: 324 threads -> B_w[a][b].
    // Half->full angle map per wire: k=0:(bi==bj)->1/2 ; k=1:(bi==bj)->(+-1/2 by bi);
    // k=2:(bi!=bj)->1/2.  => contributions only at j = i ^ xmask, sign from smask.
    if (tid < 324) {
        int w = tid / 81, idx = tid % 81;
        int a = idx / 9, b = idx % 9;
        int k0 = a / 3, k2 = a % 3, k1 = b / 3, k3 = b % 3;
        int xmask = ((k0 == 2) ? 8 : 0) | ((k1 == 2) ? 4 : 0) |
                    ((k2 == 2) ? 2 : 0) | ((k3 == 2) ? 1 : 0);
        int smask = ((k0 == 1) ? 8 : 0) | ((k1 == 1) ? 4 : 0) |
                    ((k2 == 1) ? 2 : 0) | ((k3 == 1) ? 1 : 0);
        float sum = 0.f;
#pragma unroll
        for (int i = 0; i < 16; i++) {
            float sgn = (__popc(i & smask) & 1) ? -1.f : 1.f;
            sum += sgn * shA[w][i][i ^ xmask];
        }
        d_B[tid] = sum * (1.f / 16.f);
    }
}

// ------------------------------- main kernel -------------------------------
// Grid: (32 row-groups, 32 batches), block 128 threads.
// Thread (ti = t/32, tj = t%32): row i = bx*4+ti, patches j0..j0+3 (j0 = 4*tj).
// Needs pixels rows i,i+1, cols j0..j0+4 -> 5 column P-vectors.
__global__ __launch_bounds__(128) void qconv_main(const float* __restrict__ x,
                                                  float* __restrict__ out) {
    __shared__ float sB[4 * 81];
    for (int idx = threadIdx.x; idx < 324; idx += 128) sB[idx] = d_B[idx];
    __syncthreads();

    const int b  = blockIdx.y;
    const int ti = threadIdx.x >> 5;
    const int tj = threadIdx.x & 31;
    const int i  = blockIdx.x * 4 + ti;   // output row (0..127; 127 invalid)
    const int j0 = tj * 4;
    const int i0 = (i < 126) ? i : 126;   // clamp for loads

    const float* xb = x + b * 16384;

    // per-pixel sincos for 5 columns x 2 rows
    float P[5][9];
#pragma unroll
    for (int c = 0; c < 5; c++) {
        int j = j0 + c; if (j > 127) j = 127;
        float st, ct, sb_, cb;
        __sincosf(xb[i0 * 128 + j], &st, &ct);
        __sincosf(xb[(i0 + 1) * 128 + j], &sb_, &cb);
        P[c][0] = 1.f;
        P[c][1] = cb;       P[c][2] = sb_;
        P[c][3] = ct;       P[c][4] = ct * cb;  P[c][5] = ct * sb_;
        P[c][6] = st;       P[c][7] = st * cb;  P[c][8] = st * sb_;
    }

    const bool rowok = (i < 127);

#pragma unroll
    for (int w = 0; w < 4; w++) {
        float z0 = 0.f, z1 = 0.f, z2 = 0.f, z3 = 0.f;
#pragma unroll
        for (int a = 0; a < 9; a++) {
            float y0 = 0.f, y1 = 0.f, y2 = 0.f, y3 = 0.f;
#pragma unroll
            for (int bb = 0; bb < 9; bb++) {
                float coef = sB[w * 81 + a * 9 + bb];
                y0 = fmaf(coef, P[1][bb], y0);
                y1 = fmaf(coef, P[2][bb], y1);
                y2 = fmaf(coef, P[3][bb], y2);
                y3 = fmaf(coef, P[4][bb], y3);
            }
            z0 = fmaf(P[0][a], y0, z0);
            z1 = fmaf(P[1][a], y1, z1);
            z2 = fmaf(P[2][a], y2, z2);
            z3 = fmaf(P[3][a], y3, z3);
        }
        if (rowok) {
            float* orow = out + ((size_t)(b * 4 + w) * 127 + i) * 127;
            if (j0 + 0 < 127) orow[j0 + 0] = z0;
            if (j0 + 1 < 127) orow[j0 + 1] = z1;
            if (j0 + 2 < 127) orow[j0 + 2] = z2;
            if (j0 + 3 < 127) orow[j0 + 3] = z3;
        }
    }
}

// ------------------------------- launcher ----------------------------------
extern "C" void kernel_launch(void* const* d_in, const int* in_sizes, int n_in,
                              void* d_out, int out_size) {
    const float* x      = (const float*)d_in[0];
    const float* params = (const float*)d_in[1];
    // Safety: identify params by element count (16) in case of input reorder.
    if (n_in >= 2 && in_sizes[0] == 16) {
        params = (const float*)d_in[0];
        x      = (const float*)d_in[1];
    }
    float* out = (float*)d_out;

    qconv_precompute<<<1, 512>>>(params);
    dim3 grid(32, 32);  // 32 row-groups (4 rows each) x 32 batches
    qconv_main<<<grid, 128>>>(x, out);
}

// round 4
// speedup vs baseline: 1.0070x; 1.0070x over previous
#include <cuda_runtime.h>
#include <math.h>

// ---------------------------------------------------------------------------
// QConv2D: 4-qubit quantum circuit on every 2x2 patch of x(32,1,128,128).
//
// Z_w(patch) = P_L^T B_w P_R with P = g_top (x) g_bot, g = (1, cos x, sin x);
// B_w (4 x 9 x 9) depends only on params. Precomputed on device once.
// Main kernel evaluates the bilinear forms with packed f32x2 FMA.
// ---------------------------------------------------------------------------

__device__ float2 d_B2[4 * 81];  // duplicated {c,c} per coefficient

__device__ __forceinline__ float2 cmul(float2 a, float2 b) {
    return make_float2(a.x * b.x - a.y * b.y, a.x * b.y + a.y * b.x);
}

// ---------------------------- precompute kernel ----------------------------
// U = G1 * G0, G_l = CNOTperm * (m0 (x) m1 (x) m2 (x) m3), m = RZ*RX per wire.
__global__ void qconv_precompute(const float* __restrict__ params) {
    __shared__ float2 shM[2][4][2][2];  // [layer][wire][row][col]
    __shared__ float2 shG[2][16][16];
    __shared__ float2 shU[16][16];
    __shared__ float  shA[4][16][16];
    int tid = threadIdx.x;

    // Step A: single-qubit matrices m = RZ(tz) * RX(tx)
    if (tid < 8) {
        int l = tid >> 2, w = tid & 3;
        float tx = params[(l * 4 + w) * 2 + 0];
        float tz = params[(l * 4 + w) * 2 + 1];
        float s, c, sz, cz;
        sincosf(0.5f * tx, &s, &c);
        sincosf(0.5f * tz, &sz, &cz);
        // e^{-iz/2} = (cz, -sz), e^{+iz/2} = (cz, sz)
        shM[l][w][0][0] = make_float2(cz * c, -sz * c);       // e^{-iz/2} c
        shM[l][w][0][1] = make_float2(-s * sz, -s * cz);      // e^{-iz/2}(-i s)
        shM[l][w][1][0] = make_float2(s * sz, -s * cz);       // e^{+iz/2}(-i s)
        shM[l][w][1][1] = make_float2(c * cz, c * sz);        // e^{+iz/2} c
    }
    __syncthreads();

    // Step B: G_l[i][j] = L_l[sigma(i)][j]; sigma from CNOT chain
    // CNOT(w+1 -> w) applied w=0,1,2: sigma(k) = s0(s1(s2(k)))
    if (tid < 256) {
        int i = tid >> 4, j = tid & 15;
        int r = i;
        if (r & 1) r ^= 2;   // w=2: cm=1, tm=2
        if (r & 2) r ^= 4;   // w=1: cm=2, tm=4
        if (r & 4) r ^= 8;   // w=0: cm=4, tm=8
#pragma unroll
        for (int l = 0; l < 2; l++) {
            float2 g = shM[l][0][(r >> 3) & 1][(j >> 3) & 1];
            g = cmul(g, shM[l][1][(r >> 2) & 1][(j >> 2) & 1]);
            g = cmul(g, shM[l][2][(r >> 1) & 1][(j >> 1) & 1]);
            g = cmul(g, shM[l][3][r & 1][j & 1]);
            shG[l][i][j] = g;
        }
    }
    __syncthreads();

    // Step C: U = G1 * G0
    if (tid < 256) {
        int i = tid >> 4, j = tid & 15;
        float2 acc = make_float2(0.f, 0.f);
#pragma unroll
        for (int m = 0; m < 16; m++) {
            float2 a = shG[1][i][m], b = shG[0][m][j];
            acc.x += a.x * b.x - a.y * b.y;
            acc.y += a.x * b.y + a.y * b.x;
        }
        shU[i][j] = acc;
    }
    __syncthreads();

    // Step D: A_w[i][j] = Re( i^{popc(i)-popc(j)} * sum_k d_w(k) conj(U[k,i]) U[k,j] )
    if (tid < 256) {
        int i = tid >> 4, j = tid & 15;
        float ar[4] = {0, 0, 0, 0}, ai[4] = {0, 0, 0, 0};
#pragma unroll
        for (int k = 0; k < 16; k++) {
            float2 ui = shU[k][i], uj = shU[k][j];
            float cr = ui.x * uj.x + ui.y * uj.y;
            float ci = ui.x * uj.y - ui.y * uj.x;
#pragma unroll
            for (int w = 0; w < 4; w++) {
                float sgn = (k & (1 << (3 - w))) ? -1.f : 1.f;
                ar[w] += sgn * cr;
                ai[w] += sgn * ci;
            }
        }
        int ph = (__popc(i) - __popc(j)) & 3;
#pragma unroll
        for (int w = 0; w < 4; w++) {
            float re;
            if (ph == 0)      re =  ar[w];
            else if (ph == 1) re = -ai[w];
            else if (ph == 2) re = -ar[w];
            else              re =  ai[w];
            shA[w][i][j] = re;
        }
    }
    __syncthreads();

    // Step E: half-angle -> full-angle basis: B_w[a][b]
    if (tid < 324) {
        int w = tid / 81, idx = tid % 81;
        int a = idx / 9, b = idx % 9;
        int k0 = a / 3, k2 = a % 3, k1 = b / 3, k3 = b % 3;
        int xmask = ((k0 == 2) ? 8 : 0) | ((k1 == 2) ? 4 : 0) |
                    ((k2 == 2) ? 2 : 0) | ((k3 == 2) ? 1 : 0);
        int smask = ((k0 == 1) ? 8 : 0) | ((k1 == 1) ? 4 : 0) |
                    ((k2 == 1) ? 2 : 0) | ((k3 == 1) ? 1 : 0);
        float sum = 0.f;
#pragma unroll
        for (int i = 0; i < 16; i++) {
            float sgn = (__popc(i & smask) & 1) ? -1.f : 1.f;
            sum += sgn * shA[w][i][i ^ xmask];
        }
        float v = sum * (1.f / 16.f);
        d_B2[tid] = make_float2(v, v);
    }
}

// ------------------------------- main kernel -------------------------------
typedef unsigned long long u64;

#define FMA2(acc, a, b) \
    asm("fma.rn.f32x2 %0, %1, %2, %0;" : "+l"(acc) : "l"(a), "l"(b))

__device__ __forceinline__ u64 pk(float lo, float hi) {
    u64 r;
    asm("mov.b64 %0, {%1, %2};" : "=l"(r) : "f"(lo), "f"(hi));
    return r;
}
__device__ __forceinline__ void upk(float& lo, float& hi, u64 v) {
    asm("mov.b64 {%0, %1}, %2;" : "=f"(lo), "=f"(hi) : "l"(v));
}

// Grid: (32 row-groups, 32 batches), block 128. Thread covers row i,
// patches j0..j0+3. Patches packed as (0,2) and (1,3) so the packed
// P-vectors are only {P0,P2}, {P1,P3}, {P2,P4}.
__global__ __launch_bounds__(128) void qconv_main(const float* __restrict__ x,
                                                  float* __restrict__ out) {
    __shared__ float2 sB2[324];
    {
        u64* dst = (u64*)sB2;
        const u64* src = (const u64*)d_B2;
        for (int idx = threadIdx.x; idx < 324; idx += 128) dst[idx] = src[idx];
    }
    __syncthreads();
    const u64* sBu = (const u64*)sB2;

    const int b  = blockIdx.y;
    const int ti = threadIdx.x >> 5;
    const int tj = threadIdx.x & 31;
    const int i  = blockIdx.x * 4 + ti;   // output row (0..127; 127 invalid)
    const int j0 = tj * 4;
    const int i0 = (i < 126) ? i : 126;   // clamp for loads

    const float* xb = x + b * 16384;

    // Build per-column 9-vectors g_top (x) g_bot, then pack.
    float P[5][9];
#pragma unroll
    for (int c = 0; c < 5; c++) {
        int j = j0 + c; if (j > 127) j = 127;
        float st, ct, sbt, cbt;
        __sincosf(xb[i0 * 128 + j], &st, &ct);
        __sincosf(xb[(i0 + 1) * 128 + j], &sbt, &cbt);
        P[c][0] = 1.f;
        P[c][1] = cbt;      P[c][2] = sbt;
        P[c][3] = ct;       P[c][4] = ct * cbt;  P[c][5] = ct * sbt;
        P[c][6] = st;       P[c][7] = st * cbt;  P[c][8] = st * sbt;
    }
    u64 PA[9], PB[9], PC[9];   // {P0,P2}, {P1,P3}, {P2,P4}
#pragma unroll
    for (int k = 0; k < 9; k++) {
        PA[k] = pk(P[0][k], P[2][k]);
        PB[k] = pk(P[1][k], P[3][k]);
        PC[k] = pk(P[2][k], P[4][k]);
    }

    const bool rowok = (i < 127);
    float* obase = out + ((size_t)b * 4 * 127 + i) * 127 + j0;

#pragma unroll
    for (int w = 0; w < 4; w++) {
        u64 z02 = 0ull, z13 = 0ull;
#pragma unroll
        for (int a = 0; a < 9; a++) {
            u64 y02 = 0ull, y13 = 0ull;
#pragma unroll
            for (int bb = 0; bb < 9; bb++) {
                u64 cf = sBu[w * 81 + a * 9 + bb];
                FMA2(y02, cf, PB[bb]);   // right cols: {P1,P3}
                FMA2(y13, cf, PC[bb]);   // right cols: {P2,P4}
            }
            FMA2(z02, PA[a], y02);       // left cols: {P0,P2}
            FMA2(z13, PB[a], y13);       // left cols: {P1,P3}
        }
        float z0, z1, z2, z3;
        upk(z0, z2, z02);
        upk(z1, z3, z13);
        if (rowok) {
            float* orow = obase + (size_t)w * 127 * 127;
            orow[0] = z0;
            orow[1] = z1;
            orow[2] = z2;
            if (j0 + 3 < 127) orow[3] = z3;
        }
    }
}

// ------------------------------- launcher ----------------------------------
extern "C" void kernel_launch(void* const* d_in, const int* in_sizes, int n_in,
                              void* d_out, int out_size) {
    const float* x      = (const float*)d_in[0];
    const float* params = (const float*)d_in[1];
    if (n_in >= 2 && in_sizes[0] == 16) {  // robustness to input order
        params = (const float*)d_in[0];
        x      = (const float*)d_in[1];
    }
    float* out = (float*)d_out;

    qconv_precompute<<<1, 512>>>(params);
    dim3 grid(32, 32);
    qconv_main<<<grid, 128>>>(x, out);
}

// round 8
// speedup vs baseline: 1.0802x; 1.0728x over previous
#include <cuda_runtime.h>
#include <math.h>

// ---------------------------------------------------------------------------
// QConv2D: 4-qubit circuit on every 2x2 patch of x(32,1,128,128).
// Z_w(patch) = P_L^T B_w P_R,  P = g_top (x) g_bot, g=(1,cos x,sin x).
// B_w (4 x 9 x 9) depends only on params. Each block computes B redundantly
// (cheap), then evaluates 8 patches/thread with packed f32x2 FMA.
// ---------------------------------------------------------------------------

typedef unsigned long long u64;

#define FMA2(acc, a, b) \
    asm("fma.rn.f32x2 %0, %1, %2, %0;" : "+l"(acc) : "l"(a), "l"(b))
#define FMA2N(d, a, b, c) \
    asm("fma.rn.f32x2 %0, %1, %2, %3;" : "=l"(d) : "l"(a), "l"(b), "l"(c))

__device__ __forceinline__ u64 pk(float lo, float hi) {
    u64 r; asm("mov.b64 %0, {%1, %2};" : "=l"(r) : "f"(lo), "f"(hi)); return r;
}
__device__ __forceinline__ void upk(float& lo, float& hi, u64 v) {
    asm("mov.b64 {%0, %1}, %2;" : "=f"(lo), "=f"(hi) : "l"(v));
}
__device__ __forceinline__ float2 cmulf(float2 a, float2 b) {
    return make_float2(a.x * b.x - a.y * b.y, a.x * b.y + a.y * b.x);
}

// One inner row: acc = c0 + sum_{k} cf[k] * PR[k]   (all packed f32x2)
__device__ __forceinline__ u64 yrow(const u64* cf, u64 c0, const u64* PR) {
    u64 acc;
    FMA2N(acc, cf[0], PR[0], c0);
    FMA2(acc, cf[1], PR[1]);
    FMA2(acc, cf[2], PR[2]);
    FMA2(acc, cf[3], PR[3]);
    FMA2(acc, cf[4], PR[4]);
    FMA2(acc, cf[5], PR[5]);
    FMA2(acc, cf[6], PR[6]);
    FMA2(acc, cf[7], PR[7]);
    return acc;
}

// Block: 256 threads = 16 rows x 16 col-groups (8 patches each).
// Grid: (8 row-groups, 32 batches).
__global__ __launch_bounds__(256, 2) void qconv_fused(
    const float* __restrict__ x, const float* __restrict__ params,
    float* __restrict__ out)
{
    __shared__ float2 shM[2][4][2][2];
    __shared__ float2 shG[2][16][16];
    __shared__ float2 shU[16][16];
    __shared__ float  shA[4][16][16];
    // B coefficients, duplicated {c,c} as u64; row (w,a) = 10 slots:
    // slots 0..7 = b1..b8, slot 8 = b0, slot 9 = pad (80B rows, 16B aligned)
    __shared__ __align__(16) u64 sBd[4 * 9 * 10];

    const int tid = threadIdx.x;

    // ================= per-block precompute of B =================
    // Step A: single-qubit matrices m = RZ(tz)*RX(tx)
    if (tid < 8) {
        int l = tid >> 2, w = tid & 3;
        float tx = params[(l * 4 + w) * 2 + 0];
        float tz = params[(l * 4 + w) * 2 + 1];
        float s, c, sz, cz;
        sincosf(0.5f * tx, &s, &c);
        sincosf(0.5f * tz, &sz, &cz);
        shM[l][w][0][0] = make_float2(cz * c, -sz * c);
        shM[l][w][0][1] = make_float2(-s * sz, -s * cz);
        shM[l][w][1][0] = make_float2(s * sz, -s * cz);
        shM[l][w][1][1] = make_float2(c * cz, c * sz);
    }
    __syncthreads();

    // Step B: G_l = CNOTperm * (m0 (x) m1 (x) m2 (x) m3)
    {
        int i = tid >> 4, j = tid & 15;
        int r = i;
        if (r & 1) r ^= 2;
        if (r & 2) r ^= 4;
        if (r & 4) r ^= 8;
#pragma unroll
        for (int l = 0; l < 2; l++) {
            float2 g = shM[l][0][(r >> 3) & 1][(j >> 3) & 1];
            g = cmulf(g, shM[l][1][(r >> 2) & 1][(j >> 2) & 1]);
            g = cmulf(g, shM[l][2][(r >> 1) & 1][(j >> 1) & 1]);
            g = cmulf(g, shM[l][3][r & 1][j & 1]);
            shG[l][i][j] = g;
        }
    }
    __syncthreads();

    // Step C: U = G1 * G0
    {
        int i = tid >> 4, j = tid & 15;
        float2 acc = make_float2(0.f, 0.f);
#pragma unroll
        for (int m = 0; m < 16; m++) {
            float2 a = shG[1][i][m], bb = shG[0][m][j];
            acc.x += a.x * bb.x - a.y * bb.y;
            acc.y += a.x * bb.y + a.y * bb.x;
        }
        shU[i][j] = acc;
    }
    __syncthreads();

    // Step D: A_w[i][j] = Re( i^{popc(i)-popc(j)} sum_k d_w(k) conj(U[k,i]) U[k,j] )
    {
        int i = tid >> 4, j = tid & 15;
        float ar[4] = {0, 0, 0, 0}, ai[4] = {0, 0, 0, 0};
#pragma unroll
        for (int k = 0; k < 16; k++) {
            float2 ui = shU[k][i], uj = shU[k][j];
            float cr = ui.x * uj.x + ui.y * uj.y;
            float ci = ui.x * uj.y - ui.y * uj.x;
#pragma unroll
            for (int w = 0; w < 4; w++) {
                float sgn = (k & (1 << (3 - w))) ? -1.f : 1.f;
                ar[w] += sgn * cr;
                ai[w] += sgn * ci;
            }
        }
        int ph = (__popc(i) - __popc(j)) & 3;
#pragma unroll
        for (int w = 0; w < 4; w++) {
            float re;
            if (ph == 0)      re =  ar[w];
            else if (ph == 1) re = -ai[w];
            else if (ph == 2) re = -ar[w];
            else              re =  ai[w];
            shA[w][i][j] = re;
        }
    }
    __syncthreads();

    // Step E: half-angle -> full-angle basis, write duplicated {v,v} u64
    for (int idx = tid; idx < 324; idx += 256) {
        int w = idx / 81, r = idx % 81;
        int a = r / 9, bq = r % 9;
        int k0 = a / 3, k2 = a % 3, k1 = bq / 3, k3 = bq % 3;
        int xmask = ((k0 == 2) ? 8 : 0) | ((k1 == 2) ? 4 : 0) |
                    ((k2 == 2) ? 2 : 0) | ((k3 == 2) ? 1 : 0);
        int smask = ((k0 == 1) ? 8 : 0) | ((k1 == 1) ? 4 : 0) |
                    ((k2 == 1) ? 2 : 0) | ((k3 == 1) ? 1 : 0);
        float sum = 0.f;
#pragma unroll
        for (int i = 0; i < 16; i++) {
            float sgn = (__popc(i & smask) & 1) ? -1.f : 1.f;
            sum += sgn * shA[w][i][i ^ xmask];
        }
        float v = sum * (1.f / 16.f);
        unsigned ub = __float_as_uint(v);
        int slot = (bq == 0) ? 8 : bq - 1;
        sBd[(w * 9 + a) * 10 + slot] = ((u64)ub << 32) | ub;
    }
    __syncthreads();

    // ================= main compute: 8 patches per thread =================
    const int b  = blockIdx.y;
    const int ti = tid >> 4;
    const int tj = tid & 15;
    const int i  = blockIdx.x * 16 + ti;    // output row (127 invalid)
    const int j0 = tj * 8;
    const int i0 = (i < 126) ? i : 126;

    const float* px = x + b * 16384 + i0 * 128 + j0;

    // trig for 9 columns x 2 rows (inputs in [0,1): MUFU fast path, accurate)
    float tv[9], bv[9];
    {
        float4 a0 = *(const float4*)px;
        float4 a1 = *(const float4*)(px + 4);
        float4 b0 = *(const float4*)(px + 128);
        float4 b1 = *(const float4*)(px + 132);
        tv[0]=a0.x; tv[1]=a0.y; tv[2]=a0.z; tv[3]=a0.w;
        tv[4]=a1.x; tv[5]=a1.y; tv[6]=a1.z; tv[7]=a1.w;
        bv[0]=b0.x; bv[1]=b0.y; bv[2]=b0.z; bv[3]=b0.w;
        bv[4]=b1.x; bv[5]=b1.y; bv[6]=b1.z; bv[7]=b1.w;
        int e = (j0 + 8 <= 127) ? 8 : 7;
        tv[8] = px[e];
        bv[8] = px[128 + e];
    }
    float ct[9], st[9], cb[9], sb[9];
#pragma unroll
    for (int c = 0; c < 9; c++) {
        __sincosf(tv[c], &st[c], &ct[c]);
        __sincosf(bv[c], &sb[c], &cb[c]);
    }

    // Packed column vectors PV[c] = {P(j0+c), P(j0+c+4)}, basis idx 1..8 only
    u64 PV[5][8];
#pragma unroll
    for (int c = 0; c < 5; c++) {
        int d = c + 4;
        PV[c][0] = pk(cb[c], cb[d]);
        PV[c][1] = pk(sb[c], sb[d]);
        PV[c][2] = pk(ct[c], ct[d]);
        PV[c][3] = pk(ct[c] * cb[c], ct[d] * cb[d]);
        PV[c][4] = pk(ct[c] * sb[c], ct[d] * sb[d]);
        PV[c][5] = pk(st[c], st[d]);
        PV[c][6] = pk(st[c] * cb[c], st[d] * cb[d]);
        PV[c][7] = pk(st[c] * sb[c], st[d] * sb[d]);
    }

    const bool rowok = (i < 127);
    const bool last = (j0 + 7 >= 127);   // only patch j0+7 can be invalid
    float* ob = out + ((size_t)(b * 4) * 127 + i) * 127 + j0;

#pragma unroll
    for (int w = 0; w < 4; w++) {
        u64 z0 = 0, z1 = 0, z2 = 0, z3 = 0;
#pragma unroll
        for (int a = 0; a < 9; a++) {
            const u64* rp = sBd + (w * 9 + a) * 10;
            u64 cf[8];
            // 4 x LDS.128 (16B-aligned: row stride 80B, base 16B-aligned)
            *(ulonglong2*)(cf + 0) = *(const ulonglong2*)(rp + 0);
            *(ulonglong2*)(cf + 2) = *(const ulonglong2*)(rp + 2);
            *(ulonglong2*)(cf + 4) = *(const ulonglong2*)(rp + 4);
            *(ulonglong2*)(cf + 6) = *(const ulonglong2*)(rp + 6);
            u64 c0 = rp[8];
            u64 y0 = yrow(cf, c0, PV[1]);
            u64 y1 = yrow(cf, c0, PV[2]);
            u64 y2 = yrow(cf, c0, PV[3]);
            u64 y3 = yrow(cf, c0, PV[4]);
            if (a == 0) {
                z0 = y0; z1 = y1; z2 = y2; z3 = y3;
            } else {
                FMA2(z0, PV[0][a - 1], y0);
                FMA2(z1, PV[1][a - 1], y1);
                FMA2(z2, PV[2][a - 1], y2);
                FMA2(z3, PV[3][a - 1], y3);
            }
        }
        if (rowok) {
            float* orow = ob + (size_t)w * (127 * 127);
            float lo, hi;
            upk(lo, hi, z0); orow[0] = lo; orow[4] = hi;
            upk(lo, hi, z1); orow[1] = lo; orow[5] = hi;
            upk(lo, hi, z2); orow[2] = lo; orow[6] = hi;
            upk(lo, hi, z3); orow[3] = lo;
            if (!last) orow[7] = hi;
        }
    }
}

// ------------------------------- launcher ----------------------------------
extern "C" void kernel_launch(void* const* d_in, const int* in_sizes, int n_in,
                              void* d_out, int out_size) {
    const float* x      = (const float*)d_in[0];
    const float* params = (const float*)d_in[1];
    if (n_in >= 2 && in_sizes[0] == 16) {  // robustness to input order
        params = (const float*)d_in[0];
        x      = (const float*)d_in[1];
    }
    float* out = (float*)d_out;

    dim3 grid(8, 32);   // 8 row-groups (16 rows) x 32 batches = 256 blocks
    qconv_fused<<<grid, 256>>>(x, params, out);
}

// round 9
// speedup vs baseline: 1.0925x; 1.0113x over previous
#include <cuda_runtime.h>
#include <math.h>

// ---------------------------------------------------------------------------
// QConv2D: 4-qubit circuit on every 2x2 patch of x(32,1,128,128).
// Z_w(patch) = P_L^T B_w P_R,  P = g_top (x) g_bot, g=(1,cos x,sin x).
// B_w (4 x 9 x 9) depends only on params. Each block computes B redundantly
// (cheap, overlapped), then evaluates 4 patches/thread with packed f32x2 FMA.
// ---------------------------------------------------------------------------

typedef unsigned long long u64;

#define FMA2(acc, a, b) \
    asm("fma.rn.f32x2 %0, %1, %2, %0;" : "+l"(acc) : "l"(a), "l"(b))
#define FMA2N(d, a, b, c) \
    asm("fma.rn.f32x2 %0, %1, %2, %3;" : "=l"(d) : "l"(a), "l"(b), "l"(c))

__device__ __forceinline__ u64 pk(float lo, float hi) {
    u64 r; asm("mov.b64 %0, {%1, %2};" : "=l"(r) : "f"(lo), "f"(hi)); return r;
}
__device__ __forceinline__ void upk(float& lo, float& hi, u64 v) {
    asm("mov.b64 {%0, %1}, %2;" : "=f"(lo), "=f"(hi) : "l"(v));
}
__device__ __forceinline__ float2 cmulf(float2 a, float2 b) {
    return make_float2(a.x * b.x - a.y * b.y, a.x * b.y + a.y * b.x);
}

// acc = c0 + sum_k cf[k] * PR[k]   (packed f32x2)
__device__ __forceinline__ u64 yrow(const u64* cf, u64 c0, const u64* PR) {
    u64 acc;
    FMA2N(acc, cf[0], PR[0], c0);
    FMA2(acc, cf[1], PR[1]);
    FMA2(acc, cf[2], PR[2]);
    FMA2(acc, cf[3], PR[3]);
    FMA2(acc, cf[4], PR[4]);
    FMA2(acc, cf[5], PR[5]);
    FMA2(acc, cf[6], PR[6]);
    FMA2(acc, cf[7], PR[7]);
    return acc;
}

// Block: 256 threads = 8 rows x 32 col-groups (4 patches each).
// Grid: (16 row-groups, 32 batches) = 512 blocks.
__global__ __launch_bounds__(256, 3) void qconv_fused(
    const float* __restrict__ x, const float* __restrict__ params,
    float* __restrict__ out)
{
    __shared__ float2 shM[2][4][2][2];
    __shared__ float2 shG[2][16][16];
    __shared__ float2 shU[16][16];
    __shared__ float  shA[4][16][16];
    // B coefficients, duplicated {c,c}; row (w,a) = 10 slots:
    // 0..7 = b1..b8, 8 = b0, 9 = pad (80B rows, 16B aligned)
    __shared__ __align__(16) u64 sBd[4 * 9 * 10];

    const int tid = threadIdx.x;

    // ================= per-block precompute of B =================
    if (tid < 8) {  // single-qubit mats m = RZ(tz)*RX(tx)
        int l = tid >> 2, w = tid & 3;
        float tx = params[(l * 4 + w) * 2 + 0];
        float tz = params[(l * 4 + w) * 2 + 1];
        float s, c, sz, cz;
        sincosf(0.5f * tx, &s, &c);
        sincosf(0.5f * tz, &sz, &cz);
        shM[l][w][0][0] = make_float2(cz * c, -sz * c);
        shM[l][w][0][1] = make_float2(-s * sz, -s * cz);
        shM[l][w][1][0] = make_float2(s * sz, -s * cz);
        shM[l][w][1][1] = make_float2(c * cz, c * sz);
    }
    __syncthreads();

    {   // G_l = CNOTperm * (m0 (x) m1 (x) m2 (x) m3)
        int i = tid >> 4, j = tid & 15;
        int r = i;
        if (r & 1) r ^= 2;
        if (r & 2) r ^= 4;
        if (r & 4) r ^= 8;
#pragma unroll
        for (int l = 0; l < 2; l++) {
            float2 g = shM[l][0][(r >> 3) & 1][(j >> 3) & 1];
            g = cmulf(g, shM[l][1][(r >> 2) & 1][(j >> 2) & 1]);
            g = cmulf(g, shM[l][2][(r >> 1) & 1][(j >> 1) & 1]);
            g = cmulf(g, shM[l][3][r & 1][j & 1]);
            shG[l][i][j] = g;
        }
    }
    __syncthreads();

    {   // U = G1 * G0
        int i = tid >> 4, j = tid & 15;
        float2 acc = make_float2(0.f, 0.f);
#pragma unroll
        for (int m = 0; m < 16; m++) {
            float2 a = shG[1][i][m], bb = shG[0][m][j];
            acc.x += a.x * bb.x - a.y * bb.y;
            acc.y += a.x * bb.y + a.y * bb.x;
        }
        shU[i][j] = acc;
    }
    __syncthreads();

    {   // A_w[i][j] = Re( i^{popc(i)-popc(j)} sum_k d_w(k) conj(U[k,i]) U[k,j] )
        int i = tid >> 4, j = tid & 15;
        float ar[4] = {0, 0, 0, 0}, ai[4] = {0, 0, 0, 0};
#pragma unroll
        for (int k = 0; k < 16; k++) {
            float2 ui = shU[k][i], uj = shU[k][j];
            float cr = ui.x * uj.x + ui.y * uj.y;
            float ci = ui.x * uj.y - ui.y * uj.x;
#pragma unroll
            for (int w = 0; w < 4; w++) {
                float sgn = (k & (1 << (3 - w))) ? -1.f : 1.f;
                ar[w] += sgn * cr;
                ai[w] += sgn * ci;
            }
        }
        int ph = (__popc(i) - __popc(j)) & 3;
#pragma unroll
        for (int w = 0; w < 4; w++) {
            float re;
            if (ph == 0)      re =  ar[w];
            else if (ph == 1) re = -ai[w];
            else if (ph == 2) re = -ar[w];
            else              re =  ai[w];
            shA[w][i][j] = re;
        }
    }
    __syncthreads();

    // half-angle -> full-angle basis, write duplicated {v,v}
    for (int idx = tid; idx < 324; idx += 256) {
        int w = idx / 81, r = idx % 81;
        int a = r / 9, bq = r % 9;
        int k0 = a / 3, k2 = a % 3, k1 = bq / 3, k3 = bq % 3;
        int xmask = ((k0 == 2) ? 8 : 0) | ((k1 == 2) ? 4 : 0) |
                    ((k2 == 2) ? 2 : 0) | ((k3 == 2) ? 1 : 0);
        int smask = ((k0 == 1) ? 8 : 0) | ((k1 == 1) ? 4 : 0) |
                    ((k2 == 1) ? 2 : 0) | ((k3 == 1) ? 1 : 0);
        float sum = 0.f;
#pragma unroll
        for (int i = 0; i < 16; i++) {
            float sgn = (__popc(i & smask) & 1) ? -1.f : 1.f;
            sum += sgn * shA[w][i][i ^ xmask];
        }
        float v = sum * (1.f / 16.f);
        unsigned ub = __float_as_uint(v);
        int slot = (bq == 0) ? 8 : bq - 1;
        sBd[(w * 9 + a) * 10 + slot] = ((u64)ub << 32) | ub;
    }
    __syncthreads();

    // ================= main compute: 4 patches per thread =================
    const int b  = blockIdx.y;
    const int ti = tid >> 5;               // 0..7
    const int tj = tid & 31;               // 0..31
    const int i  = blockIdx.x * 8 + ti;    // output row (127 invalid)
    const int j0 = tj * 4;
    const int i0 = (i < 126) ? i : 126;

    const float* px = x + b * 16384 + i0 * 128 + j0;

    // trig for 5 columns x 2 rows
    float tv[5], bv[5];
    {
        float4 t4 = *(const float4*)px;
        float4 b4 = *(const float4*)(px + 128);
        tv[0]=t4.x; tv[1]=t4.y; tv[2]=t4.z; tv[3]=t4.w;
        bv[0]=b4.x; bv[1]=b4.y; bv[2]=b4.z; bv[3]=b4.w;
        int e = (j0 + 4 <= 127) ? 4 : 3;
        tv[4] = px[e];
        bv[4] = px[128 + e];
    }
    float ct[5], st[5], cb[5], sb[5];
#pragma unroll
    for (int c = 0; c < 5; c++) {
        __sincosf(tv[c], &st[c], &ct[c]);
        __sincosf(bv[c], &sb[c], &cb[c]);
    }

    // Packed column vectors for pairs (0,2), (1,3), (2,4); basis idx 1..8
    u64 PA[8], PB[8], PC[8];
#pragma unroll
    for (int q = 0; q < 3; q++) {
        u64* P = (q == 0) ? PA : (q == 1) ? PB : PC;
        int c = q, d = q + 2;
        P[0] = pk(cb[c], cb[d]);
        P[1] = pk(sb[c], sb[d]);
        P[2] = pk(ct[c], ct[d]);
        P[3] = pk(ct[c] * cb[c], ct[d] * cb[d]);
        P[4] = pk(ct[c] * sb[c], ct[d] * sb[d]);
        P[5] = pk(st[c], st[d]);
        P[6] = pk(st[c] * cb[c], st[d] * cb[d]);
        P[7] = pk(st[c] * sb[c], st[d] * sb[d]);
    }

    const bool rowok = (i < 127);
    const bool last = (j0 + 3 >= 127);     // only patch j0+3 can be invalid
    float* ob = out + ((size_t)(b * 4) * 127 + i) * 127 + j0;

#pragma unroll 1
    for (int w = 0; w < 4; w++) {
        u64 z02 = 0, z13 = 0;
        const u64* wp = sBd + w * 90;
#pragma unroll
        for (int a = 0; a < 9; a++) {
            const u64* rp = wp + a * 10;
            u64 cf[8];
            *(ulonglong2*)(cf + 0) = *(const ulonglong2*)(rp + 0);
            *(ulonglong2*)(cf + 2) = *(const ulonglong2*)(rp + 2);
            *(ulonglong2*)(cf + 4) = *(const ulonglong2*)(rp + 4);
            *(ulonglong2*)(cf + 6) = *(const ulonglong2*)(rp + 6);
            u64 c0 = rp[8];
            u64 y02 = yrow(cf, c0, PB);   // right cols {1,3}
            u64 y13 = yrow(cf, c0, PC);   // right cols {2,4}
            if (a == 0) {
                z02 = y02; z13 = y13;
            } else {
                FMA2(z02, PA[a - 1], y02);  // left cols {0,2}
                FMA2(z13, PB[a - 1], y13);  // left cols {1,3}
            }
        }
        if (rowok) {
            float* orow = ob + (size_t)w * (127 * 127);
            float lo, hi;
            upk(lo, hi, z02); orow[0] = lo; orow[2] = hi;
            upk(lo, hi, z13); orow[1] = lo;
            if (!last) orow[3] = hi;
        }
    }
}

// ------------------------------- launcher ----------------------------------
extern "C" void kernel_launch(void* const* d_in, const int* in_sizes, int n_in,
                              void* d_out, int out_size) {
    const float* x      = (const float*)d_in[0];
    const float* params = (const float*)d_in[1];
    if (n_in >= 2 && in_sizes[0] == 16) {  // robustness to input order
        params = (const float*)d_in[0];
        x      = (const float*)d_in[1];
    }
    float* out = (float*)d_out;

    dim3 grid(16, 32);   // 16 row-groups (8 rows) x 32 batches = 512 blocks
    qconv_fused<<<grid, 256>>>(x, params, out);
}